// round 2
// baseline (speedup 1.0000x reference)
#include <cuda_runtime.h>
#include <math.h>

#define HDIM 1024
#define SDIM 2048
#define VDIM 50257
#define IN0  2048
#define NRED 64

// ---- scratch (no allocations allowed) ----
__device__ float g_x[IN0];        // [emb[word], last_context]
__device__ float g_h0[HDIM];      // layer-0 new hidden
__device__ float g_cat[2 * HDIM]; // [h1, context] -> input to W_out GEMV
__device__ float g_energies[SDIM];
__device__ float g_attn[SDIM];
__device__ float g_logits[VDIM];
__device__ float g_red_m[NRED];
__device__ float g_red_s[NRED];
__device__ float g_lse;

__device__ __forceinline__ float warpSum(float v) {
#pragma unroll
    for (int o = 16; o > 0; o >>= 1) v += __shfl_down_sync(0xffffffffu, v, o);
    return v;
}
__device__ __forceinline__ float warpMax(float v) {
#pragma unroll
    for (int o = 16; o > 0; o >>= 1) v = fmaxf(v, __shfl_down_sync(0xffffffffu, v, o));
    return v;
}
__device__ __forceinline__ float dot4(float4 a, float4 b) {
    return a.x * b.x + a.y * b.y + a.z * b.z + a.w * b.w;
}

// ---- 1. rnn_input = [emb[word], last_context] ----
__global__ void k_prep(const int* __restrict__ word,
                       const float* __restrict__ emb,
                       const float* __restrict__ last_context) {
    int t = blockIdx.x * blockDim.x + threadIdx.x;
    int idx = word[0];
    if (t < HDIM)            g_x[t] = emb[(size_t)idx * HDIM + t];
    else if (t < 2 * HDIM)   g_x[t] = last_context[t - HDIM];
}

// ---- 2/3. fused GRU cell: one block per hidden unit, 6 dot products ----
// LAYER 0: x = g_x (IN=2048), hout = g_h0
// LAYER 1: x = g_h0 (IN=1024), hout = g_cat[0:H]
template <int IN, int LAYER>
__global__ void k_gru(const float* __restrict__ Wih, const float* __restrict__ Whh,
                      const float* __restrict__ bih, const float* __restrict__ bhh,
                      const float* __restrict__ hprev, float* __restrict__ dout_h) {
    const int j = blockIdx.x;      // hidden unit
    const int tid = threadIdx.x;   // 256 threads
    const float* x = (LAYER == 0) ? g_x : g_h0;
    const float4* x4 = (const float4*)x;
    const float4* h4 = (const float4*)hprev;
    const float4* wr = (const float4*)(Wih + (size_t)j * IN);
    const float4* wz = (const float4*)(Wih + (size_t)(HDIM + j) * IN);
    const float4* wn = (const float4*)(Wih + (size_t)(2 * HDIM + j) * IN);
    const float4* ur = (const float4*)(Whh + (size_t)j * HDIM);
    const float4* uz = (const float4*)(Whh + (size_t)(HDIM + j) * HDIM);
    const float4* un = (const float4*)(Whh + (size_t)(2 * HDIM + j) * HDIM);

    float s0 = 0.f, s1 = 0.f, s2 = 0.f, s3 = 0.f, s4 = 0.f, s5 = 0.f;
#pragma unroll 2
    for (int k = tid; k < IN / 4; k += 256) {
        float4 xv = x4[k];
        s0 += dot4(wr[k], xv);
        s1 += dot4(wz[k], xv);
        s2 += dot4(wn[k], xv);
    }
    for (int k = tid; k < HDIM / 4; k += 256) {
        float4 hv = h4[k];
        s3 += dot4(ur[k], hv);
        s4 += dot4(uz[k], hv);
        s5 += dot4(un[k], hv);
    }

    __shared__ float sh[6][8];
    int lane = tid & 31, w = tid >> 5;
    float v;
    v = warpSum(s0); if (lane == 0) sh[0][w] = v;
    v = warpSum(s1); if (lane == 0) sh[1][w] = v;
    v = warpSum(s2); if (lane == 0) sh[2][w] = v;
    v = warpSum(s3); if (lane == 0) sh[3][w] = v;
    v = warpSum(s4); if (lane == 0) sh[4][w] = v;
    v = warpSum(s5); if (lane == 0) sh[5][w] = v;
    __syncthreads();
    if (tid == 0) {
        float t[6];
#pragma unroll
        for (int i = 0; i < 6; i++) {
            float a = 0.f;
#pragma unroll
            for (int q = 0; q < 8; q++) a += sh[i][q];
            t[i] = a;
        }
        float r = 1.f / (1.f + expf(-(t[0] + bih[j] + t[3] + bhh[j])));
        float z = 1.f / (1.f + expf(-(t[1] + bih[HDIM + j] + t[4] + bhh[HDIM + j])));
        float n = tanhf(t[2] + bih[2 * HDIM + j] + r * (t[5] + bhh[2 * HDIM + j]));
        float hnew = (1.f - z) * n + z * hprev[j];
        if (LAYER == 0) g_h0[j] = hnew; else g_cat[j] = hnew;
        dout_h[j] = hnew;
    }
}

// ---- 4. energies[s] = enc[s] . h1 ----
__global__ void k_energy(const float* __restrict__ enc) {
    int s = blockIdx.x;
    int tid = threadIdx.x; // 128
    const float4* e4 = (const float4*)(enc + (size_t)s * HDIM);
    const float4* q4 = (const float4*)g_cat; // h1 lives at g_cat[0:H]
    float acc = 0.f;
#pragma unroll
    for (int k = tid; k < HDIM / 4; k += 128) acc += dot4(e4[k], q4[k]);
    acc = warpSum(acc);
    __shared__ float sh[4];
    if ((tid & 31) == 0) sh[tid >> 5] = acc;
    __syncthreads();
    if (tid == 0) g_energies[s] = sh[0] + sh[1] + sh[2] + sh[3];
}

// ---- 5. softmax over 2048 energies (single block, 1024 threads) ----
__global__ void k_softmax(float* __restrict__ dout_attn) {
    int tid = threadIdx.x;
    int lane = tid & 31, w = tid >> 5;
    float a = g_energies[tid], b = g_energies[tid + 1024];
    __shared__ float sh[32];

    float m = fmaxf(a, b);
    m = warpMax(m);
    if (lane == 0) sh[w] = m;
    __syncthreads();
    if (w == 0) {
        float v2 = sh[lane];
        v2 = warpMax(v2);
        if (lane == 0) sh[0] = v2;
    }
    __syncthreads();
    float M = sh[0];
    __syncthreads();

    float e0 = expf(a - M), e1 = expf(b - M);
    float ssum = e0 + e1;
    ssum = warpSum(ssum);
    if (lane == 0) sh[w] = ssum;
    __syncthreads();
    if (w == 0) {
        float v2 = sh[lane];
        v2 = warpSum(v2);
        if (lane == 0) sh[0] = v2;
    }
    __syncthreads();
    float inv = 1.f / sh[0];
    float w0 = e0 * inv, w1 = e1 * inv;
    g_attn[tid] = w0;        g_attn[tid + 1024] = w1;
    dout_attn[tid] = w0;     dout_attn[tid + 1024] = w1;
}

// ---- 6. context[h] = sum_s attn[s] * enc[s][h]  (4 blocks x 256) ----
__global__ void k_context(const float* __restrict__ enc, float* __restrict__ dout_ctx) {
    __shared__ float sa[SDIM];
    int tid = threadIdx.x; // 256
    for (int i = tid; i < SDIM; i += 256) sa[i] = g_attn[i];
    __syncthreads();
    int h = blockIdx.x * 256 + tid;
    float acc = 0.f;
#pragma unroll 8
    for (int s = 0; s < SDIM; s++) acc += sa[s] * enc[(size_t)s * HDIM + h];
    g_cat[HDIM + h] = acc;
    dout_ctx[h] = acc;
}

// ---- 7. logits = W_out @ cat + b_out  (warp per row; the 412MB kernel) ----
__global__ void k_logits(const float* __restrict__ Wout, const float* __restrict__ bout) {
    int warp = (blockIdx.x * blockDim.x + threadIdx.x) >> 5;
    int lane = threadIdx.x & 31;
    if (warp >= VDIM) return;
    const float4* w4 = (const float4*)(Wout + (size_t)warp * (2 * HDIM));
    const float4* c4 = (const float4*)g_cat;
    float acc = 0.f;
#pragma unroll
    for (int k = lane; k < 512; k += 32) acc += dot4(w4[k], c4[k]);
    acc = warpSum(acc);
    if (lane == 0) g_logits[warp] = acc + bout[warp];
}

// ---- 8. partial online (max, sumexp) over logits ----
__global__ void k_red() {
    int tid = blockIdx.x * blockDim.x + threadIdx.x;
    int lane = threadIdx.x & 31, w = threadIdx.x >> 5;
    float m = -INFINITY, ssum = 0.f;
    for (int v = tid; v < VDIM; v += NRED * 256) {
        float x = g_logits[v];
        if (x > m) { ssum = ssum * expf(m - x) + 1.f; m = x; }
        else       { ssum += expf(x - m); }
    }
#pragma unroll
    for (int o = 16; o > 0; o >>= 1) {
        float m2 = __shfl_down_sync(0xffffffffu, m, o);
        float s2 = __shfl_down_sync(0xffffffffu, ssum, o);
        float M = fmaxf(m, m2);
        ssum = ssum * expf(m - M) + s2 * expf(m2 - M);
        m = M;
    }
    __shared__ float shm[8], shs[8];
    if (lane == 0) { shm[w] = m; shs[w] = ssum; }
    __syncthreads();
    if (threadIdx.x == 0) {
        float M = shm[0], S = shs[0];
#pragma unroll
        for (int q = 1; q < 8; q++) {
            float M2 = fmaxf(M, shm[q]);
            S = S * expf(M - M2) + shs[q] * expf(shm[q] - M2);
            M = M2;
        }
        g_red_m[blockIdx.x] = M;
        g_red_s[blockIdx.x] = S;
    }
}

// ---- 9. final lse (1 warp handles 64 partials) ----
__global__ void k_fin() {
    int tid = threadIdx.x; // 32
    float m1 = g_red_m[tid],      s1 = g_red_s[tid];
    float m2 = g_red_m[tid + 32], s2 = g_red_s[tid + 32];
    float M = fmaxf(m1, m2);
    float S = s1 * expf(m1 - M) + s2 * expf(m2 - M);
#pragma unroll
    for (int o = 16; o > 0; o >>= 1) {
        float M2 = __shfl_down_sync(0xffffffffu, M, o);
        float S2 = __shfl_down_sync(0xffffffffu, S, o);
        float Mc = fmaxf(M, M2);
        S = S * expf(M - Mc) + S2 * expf(M2 - Mc);
        M = Mc;
    }
    if (tid == 0) g_lse = M + logf(S);
}

// ---- 10. write log-softmax ----
__global__ void k_out(float* __restrict__ dout) {
    int v = blockIdx.x * blockDim.x + threadIdx.x;
    if (v < VDIM) dout[v] = g_logits[v] - g_lse;
}

extern "C" void kernel_launch(void* const* d_in, const int* in_sizes, int n_in,
                              void* d_out, int out_size) {
    const int*   word         = (const int*)d_in[0];
    const float* last_context = (const float*)d_in[1];
    const float* last_hidden  = (const float*)d_in[2];   // (2,1,H)
    const float* enc          = (const float*)d_in[3];   // (S,1,H)
    const float* Wih0 = (const float*)d_in[5];
    const float* Whh0 = (const float*)d_in[6];
    const float* bih0 = (const float*)d_in[7];
    const float* bhh0 = (const float*)d_in[8];
    const float* Wih1 = (const float*)d_in[9];
    const float* Whh1 = (const float*)d_in[10];
    const float* bih1 = (const float*)d_in[11];
    const float* bhh1 = (const float*)d_in[12];
    const float* Wout = (const float*)d_in[13];
    const float* bout = (const float*)d_in[14];
    const float* emb  = (const float*)d_in[4];

    float* out       = (float*)d_out;
    float* out_ctx   = out + VDIM;                 // context (H)
    float* out_h0    = out + VDIM + HDIM;          // hidden[0] (H)
    float* out_h1    = out + VDIM + 2 * HDIM;      // hidden[1] (H)
    float* out_attn  = out + VDIM + 3 * HDIM;      // attn (S)

    k_prep<<<2, 1024>>>(word, emb, last_context);
    k_gru<IN0, 0><<<HDIM, 256>>>(Wih0, Whh0, bih0, bhh0, last_hidden,        out_h0);
    k_gru<HDIM, 1><<<HDIM, 256>>>(Wih1, Whh1, bih1, bhh1, last_hidden + HDIM, out_h1);
    k_energy<<<SDIM, 128>>>(enc);
    k_softmax<<<1, 1024>>>(out_attn);
    k_context<<<HDIM / 256, 256>>>(enc, out_ctx);
    k_logits<<<(VDIM + 7) / 8, 256>>>(Wout, bout);
    k_red<<<NRED, 256>>>();
    k_fin<<<1, 32>>>();
    k_out<<<(VDIM + 255) / 256, 256>>>(out);
}

// round 3
// speedup vs baseline: 1.5454x; 1.5454x over previous
#include <cuda_runtime.h>
#include <math.h>

#define HDIM 1024
#define SDIM 2048
#define VDIM 50257
#define IN0  2048
#define NRED 64
#define SCH  32            // s-chunks for context partials

// ---- scratch (no allocations allowed) ----
__device__ float g_x[IN0];        // [emb[word], last_context]
__device__ float g_h0[HDIM];      // layer-0 new hidden
__device__ float g_cat[2 * HDIM]; // [h1, context] -> input to W_out GEMV
__device__ float g_energies[SDIM];
__device__ float g_attn[SDIM];
__device__ float g_ctx_part[SCH * HDIM];
__device__ float g_logits[VDIM];
__device__ float g_red_m[NRED];
__device__ float g_red_s[NRED];

__device__ __forceinline__ float warpSum(float v) {
#pragma unroll
    for (int o = 16; o > 0; o >>= 1) v += __shfl_down_sync(0xffffffffu, v, o);
    return v;
}
__device__ __forceinline__ float warpMax(float v) {
#pragma unroll
    for (int o = 16; o > 0; o >>= 1) v = fmaxf(v, __shfl_down_sync(0xffffffffu, v, o));
    return v;
}
__device__ __forceinline__ float dot4(float4 a, float4 b) {
    return a.x * b.x + a.y * b.y + a.z * b.z + a.w * b.w;
}

// ---- 1. rnn_input = [emb[word], last_context] ----
__global__ void k_prep(const int* __restrict__ word,
                       const float* __restrict__ emb,
                       const float* __restrict__ last_context) {
    int t = blockIdx.x * blockDim.x + threadIdx.x;
    int idx = word[0];
    if (t < HDIM)            g_x[t] = emb[(size_t)idx * HDIM + t];
    else if (t < 2 * HDIM)   g_x[t] = last_context[t - HDIM];
}

// ---- 2/3. fused GRU cell: one block per hidden unit, 6 dot products ----
template <int IN, int LAYER>
__global__ void k_gru(const float* __restrict__ Wih, const float* __restrict__ Whh,
                      const float* __restrict__ bih, const float* __restrict__ bhh,
                      const float* __restrict__ hprev, float* __restrict__ dout_h) {
    const int j = blockIdx.x;      // hidden unit
    const int tid = threadIdx.x;   // 256 threads
    const float* x = (LAYER == 0) ? g_x : g_h0;
    const float4* x4 = (const float4*)x;
    const float4* h4 = (const float4*)hprev;
    const float4* wr = (const float4*)(Wih + (size_t)j * IN);
    const float4* wz = (const float4*)(Wih + (size_t)(HDIM + j) * IN);
    const float4* wn = (const float4*)(Wih + (size_t)(2 * HDIM + j) * IN);
    const float4* ur = (const float4*)(Whh + (size_t)j * HDIM);
    const float4* uz = (const float4*)(Whh + (size_t)(HDIM + j) * HDIM);
    const float4* un = (const float4*)(Whh + (size_t)(2 * HDIM + j) * HDIM);

    float s0 = 0.f, s1 = 0.f, s2 = 0.f, s3 = 0.f, s4 = 0.f, s5 = 0.f;
#pragma unroll 2
    for (int k = tid; k < IN / 4; k += 256) {
        float4 xv = x4[k];
        s0 += dot4(wr[k], xv);
        s1 += dot4(wz[k], xv);
        s2 += dot4(wn[k], xv);
    }
    for (int k = tid; k < HDIM / 4; k += 256) {
        float4 hv = h4[k];
        s3 += dot4(ur[k], hv);
        s4 += dot4(uz[k], hv);
        s5 += dot4(un[k], hv);
    }

    __shared__ float sh[6][8];
    int lane = tid & 31, w = tid >> 5;
    float v;
    v = warpSum(s0); if (lane == 0) sh[0][w] = v;
    v = warpSum(s1); if (lane == 0) sh[1][w] = v;
    v = warpSum(s2); if (lane == 0) sh[2][w] = v;
    v = warpSum(s3); if (lane == 0) sh[3][w] = v;
    v = warpSum(s4); if (lane == 0) sh[4][w] = v;
    v = warpSum(s5); if (lane == 0) sh[5][w] = v;
    __syncthreads();
    if (tid == 0) {
        float t[6];
#pragma unroll
        for (int i = 0; i < 6; i++) {
            float a = 0.f;
#pragma unroll
            for (int q = 0; q < 8; q++) a += sh[i][q];
            t[i] = a;
        }
        float r = 1.f / (1.f + expf(-(t[0] + bih[j] + t[3] + bhh[j])));
        float z = 1.f / (1.f + expf(-(t[1] + bih[HDIM + j] + t[4] + bhh[HDIM + j])));
        float n = tanhf(t[2] + bih[2 * HDIM + j] + r * (t[5] + bhh[2 * HDIM + j]));
        float hnew = (1.f - z) * n + z * hprev[j];
        if (LAYER == 0) g_h0[j] = hnew; else g_cat[j] = hnew;
        dout_h[j] = hnew;
    }
}

// ---- 4. energies[s] = enc[s] . h1  (warp per row: 8 float4 in flight/lane) ----
__global__ void k_energy(const float* __restrict__ enc) {
    int warp = (blockIdx.x * blockDim.x + threadIdx.x) >> 5;  // row s
    int lane = threadIdx.x & 31;
    const float4* e4 = (const float4*)(enc + (size_t)warp * HDIM);
    const float4* q4 = (const float4*)g_cat;  // h1
    float acc = 0.f;
#pragma unroll
    for (int k = lane; k < HDIM / 4; k += 32) acc += dot4(e4[k], q4[k]);
    acc = warpSum(acc);
    if (lane == 0) g_energies[warp] = acc;
}

// ---- 5. softmax over 2048 energies (single block, 1024 threads) ----
__global__ void k_softmax(float* __restrict__ dout_attn) {
    int tid = threadIdx.x;
    int lane = tid & 31, w = tid >> 5;
    float a = g_energies[tid], b = g_energies[tid + 1024];
    __shared__ float sh[32];

    float m = fmaxf(a, b);
    m = warpMax(m);
    if (lane == 0) sh[w] = m;
    __syncthreads();
    if (w == 0) {
        float v2 = sh[lane];
        v2 = warpMax(v2);
        if (lane == 0) sh[0] = v2;
    }
    __syncthreads();
    float M = sh[0];
    __syncthreads();

    float e0 = expf(a - M), e1 = expf(b - M);
    float ssum = e0 + e1;
    ssum = warpSum(ssum);
    if (lane == 0) sh[w] = ssum;
    __syncthreads();
    if (w == 0) {
        float v2 = sh[lane];
        v2 = warpSum(v2);
        if (lane == 0) sh[0] = v2;
    }
    __syncthreads();
    float inv = 1.f / sh[0];
    float w0 = e0 * inv, w1 = e1 * inv;
    g_attn[tid] = w0;        g_attn[tid + 1024] = w1;
    dout_attn[tid] = w0;     dout_attn[tid + 1024] = w1;
}

// ---- 6a. context partials: grid (4 h-chunks, SCH s-chunks) ----
__global__ void k_context_part(const float* __restrict__ enc) {
    __shared__ float sa[SDIM / SCH];          // 64 attn weights
    const int tid = threadIdx.x;              // 256
    const int s0 = blockIdx.y * (SDIM / SCH);
    if (tid < SDIM / SCH) sa[tid] = g_attn[s0 + tid];
    __syncthreads();
    const int h = blockIdx.x * 256 + tid;
    const float* e = enc + (size_t)s0 * HDIM + h;
    float acc = 0.f;
#pragma unroll 8
    for (int s = 0; s < SDIM / SCH; s++) acc += sa[s] * e[(size_t)s * HDIM];
    g_ctx_part[blockIdx.y * HDIM + h] = acc;
}

// ---- 6b. context reduce over SCH partials ----
__global__ void k_context_red(float* __restrict__ dout_ctx) {
    int h = blockIdx.x * 256 + threadIdx.x;
    float acc = 0.f;
#pragma unroll
    for (int c = 0; c < SCH; c++) acc += g_ctx_part[c * HDIM + h];
    g_cat[HDIM + h] = acc;
    dout_ctx[h] = acc;
}

// ---- 7. logits = W_out @ cat + b_out  (warp per row; the 412MB kernel) ----
__global__ void k_logits(const float* __restrict__ Wout, const float* __restrict__ bout) {
    int warp = (blockIdx.x * blockDim.x + threadIdx.x) >> 5;
    int lane = threadIdx.x & 31;
    if (warp >= VDIM) return;
    const float4* w4 = (const float4*)(Wout + (size_t)warp * (2 * HDIM));
    const float4* c4 = (const float4*)g_cat;
    float acc = 0.f;
#pragma unroll
    for (int k = lane; k < 512; k += 32) acc += dot4(w4[k], c4[k]);
    acc = warpSum(acc);
    if (lane == 0) g_logits[warp] = acc + bout[warp];
}

// ---- 8. partial online (max, sumexp) over logits ----
__global__ void k_red() {
    int tid = blockIdx.x * blockDim.x + threadIdx.x;
    int lane = threadIdx.x & 31, w = threadIdx.x >> 5;
    float m = -INFINITY, ssum = 0.f;
    for (int v = tid; v < VDIM; v += NRED * 256) {
        float x = g_logits[v];
        if (x > m) { ssum = ssum * expf(m - x) + 1.f; m = x; }
        else       { ssum += expf(x - m); }
    }
#pragma unroll
    for (int o = 16; o > 0; o >>= 1) {
        float m2 = __shfl_down_sync(0xffffffffu, m, o);
        float s2 = __shfl_down_sync(0xffffffffu, ssum, o);
        float M = fmaxf(m, m2);
        ssum = ssum * expf(m - M) + s2 * expf(m2 - M);
        m = M;
    }
    __shared__ float shm[8], shs[8];
    if (lane == 0) { shm[w] = m; shs[w] = ssum; }
    __syncthreads();
    if (threadIdx.x == 0) {
        float M = shm[0], S = shs[0];
#pragma unroll
        for (int q = 1; q < 8; q++) {
            float M2 = fmaxf(M, shm[q]);
            S = S * expf(M - M2) + shs[q] * expf(shm[q] - M2);
            M = M2;
        }
        g_red_m[blockIdx.x] = M;
        g_red_s[blockIdx.x] = S;
    }
}

// ---- 9. final lse (warp 0 in-block) + write log-softmax ----
__global__ void k_out(float* __restrict__ dout) {
    __shared__ float sh_lse;
    int tid = threadIdx.x;
    if (tid < 32) {
        float m1 = g_red_m[tid],      s1 = g_red_s[tid];
        float m2 = g_red_m[tid + 32], s2 = g_red_s[tid + 32];
        float M = fmaxf(m1, m2);
        float S = s1 * expf(m1 - M) + s2 * expf(m2 - M);
#pragma unroll
        for (int o = 16; o > 0; o >>= 1) {
            float M2 = __shfl_down_sync(0xffffffffu, M, o);
            float S2 = __shfl_down_sync(0xffffffffu, S, o);
            float Mc = fmaxf(M, M2);
            S = S * expf(M - Mc) + S2 * expf(M2 - Mc);
            M = Mc;
        }
        if (tid == 0) sh_lse = M + logf(S);
    }
    __syncthreads();
    float lse = sh_lse;
    int v = blockIdx.x * blockDim.x + tid;
    if (v < VDIM) dout[v] = g_logits[v] - lse;
}

extern "C" void kernel_launch(void* const* d_in, const int* in_sizes, int n_in,
                              void* d_out, int out_size) {
    const int*   word         = (const int*)d_in[0];
    const float* last_context = (const float*)d_in[1];
    const float* last_hidden  = (const float*)d_in[2];   // (2,1,H)
    const float* enc          = (const float*)d_in[3];   // (S,1,H)
    const float* emb  = (const float*)d_in[4];
    const float* Wih0 = (const float*)d_in[5];
    const float* Whh0 = (const float*)d_in[6];
    const float* bih0 = (const float*)d_in[7];
    const float* bhh0 = (const float*)d_in[8];
    const float* Wih1 = (const float*)d_in[9];
    const float* Whh1 = (const float*)d_in[10];
    const float* bih1 = (const float*)d_in[11];
    const float* bhh1 = (const float*)d_in[12];
    const float* Wout = (const float*)d_in[13];
    const float* bout = (const float*)d_in[14];

    float* out       = (float*)d_out;
    float* out_ctx   = out + VDIM;                 // context (H)
    float* out_h0    = out + VDIM + HDIM;          // hidden[0] (H)
    float* out_h1    = out + VDIM + 2 * HDIM;      // hidden[1] (H)
    float* out_attn  = out + VDIM + 3 * HDIM;      // attn (S)

    k_prep<<<2, 1024>>>(word, emb, last_context);
    k_gru<IN0, 0><<<HDIM, 256>>>(Wih0, Whh0, bih0, bhh0, last_hidden,         out_h0);
    k_gru<HDIM, 1><<<HDIM, 256>>>(Wih1, Whh1, bih1, bhh1, last_hidden + HDIM, out_h1);
    k_energy<<<SDIM / 8, 256>>>(enc);
    k_softmax<<<1, 1024>>>(out_attn);
    k_context_part<<<dim3(HDIM / 256, SCH), 256>>>(enc);
    k_context_red<<<HDIM / 256, 256>>>(out_ctx);
    k_logits<<<(VDIM + 7) / 8, 256>>>(Wout, bout);
    k_red<<<NRED, 256>>>();
    k_out<<<(VDIM + 255) / 256, 256>>>(out);
}

// round 6
// speedup vs baseline: 1.6083x; 1.0407x over previous
#include <cuda_runtime.h>
#include <math.h>

#define HDIM 1024
#define SDIM 2048
#define VDIM 50257
#define IN0  2048
#define NRED 64
#define SCH  64            // s-chunks for context partials

// ---- scratch (no allocations allowed) ----
__device__ float g_x[IN0];        // [emb[word], last_context]
__device__ float g_h0[HDIM];      // layer-0 new hidden
__device__ float g_cat[2 * HDIM]; // [h1, context] -> input to W_out GEMV
__device__ float g_energies[SDIM];
__device__ float g_attn[SDIM];
__device__ float g_ctx_part[SCH * HDIM];
__device__ float g_logits[VDIM];
__device__ float g_red_m[NRED];
__device__ float g_red_s[NRED];

__device__ __forceinline__ float warpSum(float v) {
#pragma unroll
    for (int o = 16; o > 0; o >>= 1) v += __shfl_down_sync(0xffffffffu, v, o);
    return v;
}
__device__ __forceinline__ float warpMax(float v) {
#pragma unroll
    for (int o = 16; o > 0; o >>= 1) v = fmaxf(v, __shfl_down_sync(0xffffffffu, v, o));
    return v;
}
__device__ __forceinline__ float dot4(float4 a, float4 b) {
    return a.x * b.x + a.y * b.y + a.z * b.z + a.w * b.w;
}

// ---- 1. rnn_input = [emb[word], last_context] ----
__global__ void k_prep(const int* __restrict__ word,
                       const float* __restrict__ emb,
                       const float* __restrict__ last_context) {
    int t = blockIdx.x * blockDim.x + threadIdx.x;
    int idx = word[0];
    if (t < HDIM)            g_x[t] = emb[(size_t)idx * HDIM + t];
    else if (t < 2 * HDIM)   g_x[t] = last_context[t - HDIM];
}

// ---- 2/3. fused GRU cell: one block per hidden unit, 6 dot products ----
template <int IN, int LAYER>
__global__ void k_gru(const float* __restrict__ Wih, const float* __restrict__ Whh,
                      const float* __restrict__ bih, const float* __restrict__ bhh,
                      const float* __restrict__ hprev, float* __restrict__ dout_h) {
    const int j = blockIdx.x;      // hidden unit
    const int tid = threadIdx.x;   // 256 threads
    const float* x = (LAYER == 0) ? g_x : g_h0;
    const float4* x4 = (const float4*)x;
    const float4* h4 = (const float4*)hprev;
    const float4* wr = (const float4*)(Wih + (size_t)j * IN);
    const float4* wz = (const float4*)(Wih + (size_t)(HDIM + j) * IN);
    const float4* wn = (const float4*)(Wih + (size_t)(2 * HDIM + j) * IN);
    const float4* ur = (const float4*)(Whh + (size_t)j * HDIM);
    const float4* uz = (const float4*)(Whh + (size_t)(HDIM + j) * HDIM);
    const float4* un = (const float4*)(Whh + (size_t)(2 * HDIM + j) * HDIM);

    float s0 = 0.f, s1 = 0.f, s2 = 0.f, s3 = 0.f, s4 = 0.f, s5 = 0.f;
#pragma unroll 2
    for (int k = tid; k < IN / 4; k += 256) {
        float4 xv = x4[k];
        s0 += dot4(__ldcs(wr + k), xv);
        s1 += dot4(__ldcs(wz + k), xv);
        s2 += dot4(__ldcs(wn + k), xv);
    }
    for (int k = tid; k < HDIM / 4; k += 256) {
        float4 hv = h4[k];
        s3 += dot4(__ldcs(ur + k), hv);
        s4 += dot4(__ldcs(uz + k), hv);
        s5 += dot4(__ldcs(un + k), hv);
    }

    __shared__ float sh[6][8];
    int lane = tid & 31, w = tid >> 5;
    float v;
    v = warpSum(s0); if (lane == 0) sh[0][w] = v;
    v = warpSum(s1); if (lane == 0) sh[1][w] = v;
    v = warpSum(s2); if (lane == 0) sh[2][w] = v;
    v = warpSum(s3); if (lane == 0) sh[3][w] = v;
    v = warpSum(s4); if (lane == 0) sh[4][w] = v;
    v = warpSum(s5); if (lane == 0) sh[5][w] = v;
    __syncthreads();
    if (tid == 0) {
        float t[6];
#pragma unroll
        for (int i = 0; i < 6; i++) {
            float a = 0.f;
#pragma unroll
            for (int q = 0; q < 8; q++) a += sh[i][q];
            t[i] = a;
        }
        float r = 1.f / (1.f + expf(-(t[0] + bih[j] + t[3] + bhh[j])));
        float z = 1.f / (1.f + expf(-(t[1] + bih[HDIM + j] + t[4] + bhh[HDIM + j])));
        float n = tanhf(t[2] + bih[2 * HDIM + j] + r * (t[5] + bhh[2 * HDIM + j]));
        float hnew = (1.f - z) * n + z * hprev[j];
        if (LAYER == 0) g_h0[j] = hnew; else g_cat[j] = hnew;
        dout_h[j] = hnew;
    }
}

// ---- 4. energies: h1 in smem, 2 rows per warp (16 LDG.128 in flight) ----
__global__ void k_energy(const float* __restrict__ enc) {
    __shared__ float4 qs[HDIM / 4];           // 4KB: h1
    const int tid = threadIdx.x;              // 256
    qs[tid] = ((const float4*)g_cat)[tid];
    __syncthreads();
    const int warp = tid >> 5, lane = tid & 31;
    const int row0 = (blockIdx.x * 8 + warp) * 2;   // 2 rows per warp
    const float4* e0 = (const float4*)(enc + (size_t)row0 * HDIM);
    const float4* e1 = (const float4*)(enc + (size_t)(row0 + 1) * HDIM);
    float a0 = 0.f, a1 = 0.f;
#pragma unroll
    for (int k = lane; k < HDIM / 4; k += 32) {
        float4 q = qs[k];
        a0 += dot4(__ldcs(e0 + k), q);
        a1 += dot4(__ldcs(e1 + k), q);
    }
    a0 = warpSum(a0);
    a1 = warpSum(a1);
    if (lane == 0) { g_energies[row0] = a0; g_energies[row0 + 1] = a1; }
}

// ---- 5. softmax over 2048 energies (single block, 1024 threads) ----
__global__ void k_softmax(float* __restrict__ dout_attn) {
    int tid = threadIdx.x;
    int lane = tid & 31, w = tid >> 5;
    float a = g_energies[tid], b = g_energies[tid + 1024];
    __shared__ float sh[32];

    float m = fmaxf(a, b);
    m = warpMax(m);
    if (lane == 0) sh[w] = m;
    __syncthreads();
    if (w == 0) {
        float v2 = sh[lane];
        v2 = warpMax(v2);
        if (lane == 0) sh[0] = v2;
    }
    __syncthreads();
    float M = sh[0];
    __syncthreads();

    float e0 = expf(a - M), e1 = expf(b - M);
    float ssum = e0 + e1;
    ssum = warpSum(ssum);
    if (lane == 0) sh[w] = ssum;
    __syncthreads();
    if (w == 0) {
        float v2 = sh[lane];
        v2 = warpSum(v2);
        if (lane == 0) sh[0] = v2;
    }
    __syncthreads();
    float inv = 1.f / sh[0];
    float w0 = e0 * inv, w1 = e1 * inv;
    g_attn[tid] = w0;        g_attn[tid + 1024] = w1;
    dout_attn[tid] = w0;     dout_attn[tid + 1024] = w1;
}

// ---- 6a. context partials: grid (4 h-chunks, SCH s-chunks) ----
__global__ void k_context_part(const float* __restrict__ enc) {
    __shared__ float sa[SDIM / SCH];          // 32 attn weights
    const int tid = threadIdx.x;              // 256
    const int s0 = blockIdx.y * (SDIM / SCH);
    if (tid < SDIM / SCH) sa[tid] = g_attn[s0 + tid];
    __syncthreads();
    const int h = blockIdx.x * 256 + tid;
    const float* e = enc + (size_t)s0 * HDIM + h;
    float acc = 0.f;
#pragma unroll 8
    for (int s = 0; s < SDIM / SCH; s++) acc += sa[s] * __ldcs(e + (size_t)s * HDIM);
    g_ctx_part[blockIdx.y * HDIM + h] = acc;
}

// ---- 6b. context reduce over SCH partials ----
__global__ void k_context_red(float* __restrict__ dout_ctx) {
    int h = blockIdx.x * 256 + threadIdx.x;
    float acc = 0.f;
#pragma unroll
    for (int c = 0; c < SCH; c++) acc += g_ctx_part[c * HDIM + h];
    g_cat[HDIM + h] = acc;
    dout_ctx[h] = acc;
}

// ---- 7. logits = W_out @ cat + b_out  (warp/row; cat in smem; streaming W) ----
__global__ void k_logits(const float* __restrict__ Wout, const float* __restrict__ bout) {
    __shared__ float4 cs[512];                // 8KB: full [h1, context]
    const int tid = threadIdx.x;              // 256
    cs[tid] = ((const float4*)g_cat)[tid];
    cs[tid + 256] = ((const float4*)g_cat)[tid + 256];
    __syncthreads();
    const int warp = tid >> 5, lane = tid & 31;
    const int row = blockIdx.x * 8 + warp;
    if (row >= VDIM) return;
    const float4* w4 = (const float4*)(Wout + (size_t)row * (2 * HDIM));
    float acc = 0.f;
#pragma unroll
    for (int k = lane; k < 512; k += 32) acc += dot4(__ldcs(w4 + k), cs[k]);
    acc = warpSum(acc);
    if (lane == 0) g_logits[row] = acc + bout[row];
}

// ---- 8. partial online (max, sumexp) over logits ----
__global__ void k_red() {
    int tid = blockIdx.x * blockDim.x + threadIdx.x;
    int lane = threadIdx.x & 31, w = threadIdx.x >> 5;
    float m = -INFINITY, ssum = 0.f;
    for (int v = tid; v < VDIM; v += NRED * 256) {
        float x = g_logits[v];
        if (x > m) { ssum = ssum * expf(m - x) + 1.f; m = x; }
        else       { ssum += expf(x - m); }
    }
#pragma unroll
    for (int o = 16; o > 0; o >>= 1) {
        float m2 = __shfl_down_sync(0xffffffffu, m, o);
        float s2 = __shfl_down_sync(0xffffffffu, ssum, o);
        float M = fmaxf(m, m2);
        ssum = ssum * expf(m - M) + s2 * expf(m2 - M);
        m = M;
    }
    __shared__ float shm[8], shs[8];
    if (lane == 0) { shm[w] = m; shs[w] = ssum; }
    __syncthreads();
    if (threadIdx.x == 0) {
        float M = shm[0], S = shs[0];
#pragma unroll
        for (int q = 1; q < 8; q++) {
            float M2 = fmaxf(M, shm[q]);
            S = S * expf(M - M2) + shs[q] * expf(shm[q] - M2);
            M = M2;
        }
        g_red_m[blockIdx.x] = M;
        g_red_s[blockIdx.x] = S;
    }
}

// ---- 9. final lse (warp 0 in-block) + write log-softmax ----
__global__ void k_out(float* __restrict__ dout) {
    __shared__ float sh_lse;
    int tid = threadIdx.x;
    if (tid < 32) {
        float m1 = g_red_m[tid],      s1 = g_red_s[tid];
        float m2 = g_red_m[tid + 32], s2 = g_red_s[tid + 32];
        float M = fmaxf(m1, m2);
        float S = s1 * expf(m1 - M) + s2 * expf(m2 - M);
#pragma unroll
        for (int o = 16; o > 0; o >>= 1) {
            float M2 = __shfl_down_sync(0xffffffffu, M, o);
            float S2 = __shfl_down_sync(0xffffffffu, S, o);
            float Mc = fmaxf(M, M2);
            S = S * expf(M - Mc) + S2 * expf(M2 - Mc);
            M = Mc;
        }
        if (tid == 0) sh_lse = M + logf(S);
    }
    __syncthreads();
    float lse = sh_lse;
    int v = blockIdx.x * blockDim.x + tid;
    if (v < VDIM) dout[v] = g_logits[v] - lse;
}

extern "C" void kernel_launch(void* const* d_in, const int* in_sizes, int n_in,
                              void* d_out, int out_size) {
    const int*   word         = (const int*)d_in[0];
    const float* last_context = (const float*)d_in[1];
    const float* last_hidden  = (const float*)d_in[2];   // (2,1,H)
    const float* enc          = (const float*)d_in[3];   // (S,1,H)
    const float* emb  = (const float*)d_in[4];
    const float* Wih0 = (const float*)d_in[5];
    const float* Whh0 = (const float*)d_in[6];
    const float* bih0 = (const float*)d_in[7];
    const float* bhh0 = (const float*)d_in[8];
    const float* Wih1 = (const float*)d_in[9];
    const float* Whh1 = (const float*)d_in[10];
    const float* bih1 = (const float*)d_in[11];
    const float* bhh1 = (const float*)d_in[12];
    const float* Wout = (const float*)d_in[13];
    const float* bout = (const float*)d_in[14];

    float* out       = (float*)d_out;
    float* out_ctx   = out + VDIM;                 // context (H)
    float* out_h0    = out + VDIM + HDIM;          // hidden[0] (H)
    float* out_h1    = out + VDIM + 2 * HDIM;      // hidden[1] (H)
    float* out_attn  = out + VDIM + 3 * HDIM;      // attn (S)

    k_prep<<<2, 1024>>>(word, emb, last_context);
    k_gru<IN0, 0><<<HDIM, 256>>>(Wih0, Whh0, bih0, bhh0, last_hidden,         out_h0);
    k_gru<HDIM, 1><<<HDIM, 256>>>(Wih1, Whh1, bih1, bhh1, last_hidden + HDIM, out_h1);
    k_energy<<<SDIM / 16, 256>>>(enc);
    k_softmax<<<1, 1024>>>(out_attn);
    k_context_part<<<dim3(HDIM / 256, SCH), 256>>>(enc);
    k_context_red<<<HDIM / 256, 256>>>(out_ctx);
    k_logits<<<(VDIM + 7) / 8, 256>>>(Wout, bout);
    k_red<<<NRED, 256>>>();
    k_out<<<(VDIM + 255) / 256, 256>>>(out);
}

// round 7
// speedup vs baseline: 1.8577x; 1.1551x over previous
#include <cuda_runtime.h>
#include <math.h>

#define HDIM 1024
#define SDIM 2048
#define VDIM 50257
#define IN0  2048
#define NRED 64
#define SCH  64            // s-chunks for context partials

// ---- scratch (no allocations allowed) ----
__device__ float g_h0[HDIM];      // layer-0 new hidden
__device__ float g_cat[2 * HDIM]; // [h1, context] -> input to W_out GEMV
__device__ float g_energies[SDIM];
__device__ float g_attn[SDIM];
__device__ float g_ctx_part[SCH * HDIM];
__device__ float g_logits[VDIM];
__device__ float g_red_m[NRED];
__device__ float g_red_s[NRED];

__device__ __forceinline__ float warpSum(float v) {
#pragma unroll
    for (int o = 16; o > 0; o >>= 1) v += __shfl_down_sync(0xffffffffu, v, o);
    return v;
}
__device__ __forceinline__ float warpMax(float v) {
#pragma unroll
    for (int o = 16; o > 0; o >>= 1) v = fmaxf(v, __shfl_down_sync(0xffffffffu, v, o));
    return v;
}
__device__ __forceinline__ float dot4(float4 a, float4 b) {
    return a.x * b.x + a.y * b.y + a.z * b.z + a.w * b.w;
}

// ---- 1/2. fused GRU cell: one block per hidden unit, 6 dot products ----
// LAYER 0: x = [emb[word], last_context] gathered in-kernel (IN=2048)
// LAYER 1: x = g_h0 (IN=1024)
template <int IN, int LAYER>
__global__ void k_gru(const float* __restrict__ Wih, const float* __restrict__ Whh,
                      const float* __restrict__ bih, const float* __restrict__ bhh,
                      const float* __restrict__ hprev, float* __restrict__ dout_h,
                      const int* __restrict__ word, const float* __restrict__ emb,
                      const float* __restrict__ last_context) {
    const int j = blockIdx.x;      // hidden unit
    const int tid = threadIdx.x;   // 256 threads
    const float4* h4 = (const float4*)hprev;
    const float4* wr = (const float4*)(Wih + (size_t)j * IN);
    const float4* wz = (const float4*)(Wih + (size_t)(HDIM + j) * IN);
    const float4* wn = (const float4*)(Wih + (size_t)(2 * HDIM + j) * IN);
    const float4* ur = (const float4*)(Whh + (size_t)j * HDIM);
    const float4* uz = (const float4*)(Whh + (size_t)(HDIM + j) * HDIM);
    const float4* un = (const float4*)(Whh + (size_t)(2 * HDIM + j) * HDIM);

    const float4* x4a;   // first H floats of x
    const float4* x4b;   // second H floats (layer 0 only)
    if (LAYER == 0) {
        x4a = (const float4*)(emb + (size_t)word[0] * HDIM);
        x4b = (const float4*)last_context;
    } else {
        x4a = (const float4*)g_h0;
        x4b = nullptr;
    }

    float s0 = 0.f, s1 = 0.f, s2 = 0.f, s3 = 0.f, s4 = 0.f, s5 = 0.f;
#pragma unroll 2
    for (int k = tid; k < IN / 4; k += 256) {
        float4 xv = (LAYER == 0) ? ((k < HDIM / 4) ? x4a[k] : x4b[k - HDIM / 4])
                                 : x4a[k];
        s0 += dot4(__ldcs(wr + k), xv);
        s1 += dot4(__ldcs(wz + k), xv);
        s2 += dot4(__ldcs(wn + k), xv);
    }
    for (int k = tid; k < HDIM / 4; k += 256) {
        float4 hv = h4[k];
        s3 += dot4(__ldcs(ur + k), hv);
        s4 += dot4(__ldcs(uz + k), hv);
        s5 += dot4(__ldcs(un + k), hv);
    }

    __shared__ float sh[6][8];
    int lane = tid & 31, w = tid >> 5;
    float v;
    v = warpSum(s0); if (lane == 0) sh[0][w] = v;
    v = warpSum(s1); if (lane == 0) sh[1][w] = v;
    v = warpSum(s2); if (lane == 0) sh[2][w] = v;
    v = warpSum(s3); if (lane == 0) sh[3][w] = v;
    v = warpSum(s4); if (lane == 0) sh[4][w] = v;
    v = warpSum(s5); if (lane == 0) sh[5][w] = v;
    __syncthreads();
    if (tid == 0) {
        float t[6];
#pragma unroll
        for (int i = 0; i < 6; i++) {
            float a = 0.f;
#pragma unroll
            for (int q = 0; q < 8; q++) a += sh[i][q];
            t[i] = a;
        }
        float r = 1.f / (1.f + expf(-(t[0] + bih[j] + t[3] + bhh[j])));
        float z = 1.f / (1.f + expf(-(t[1] + bih[HDIM + j] + t[4] + bhh[HDIM + j])));
        float n = tanhf(t[2] + bih[2 * HDIM + j] + r * (t[5] + bhh[2 * HDIM + j]));
        float hnew = (1.f - z) * n + z * hprev[j];
        if (LAYER == 0) g_h0[j] = hnew; else g_cat[j] = hnew;
        dout_h[j] = hnew;
    }
}

// ---- 3. energies: 1 row/warp, EXPLICIT 8-deep load batch ----
__global__ void k_energy(const float* __restrict__ enc) {
    __shared__ float4 qs[HDIM / 4];           // 4KB: h1
    const int tid = threadIdx.x;              // 256
    qs[tid] = ((const float4*)g_cat)[tid];
    __syncthreads();
    const int warp = tid >> 5, lane = tid & 31;
    const int row = blockIdx.x * 8 + warp;
    const float4* e = (const float4*)(enc + (size_t)row * HDIM);
    float4 r[8];
#pragma unroll
    for (int i = 0; i < 8; i++) r[i] = __ldcs(e + lane + 32 * i);   // all in flight
    float acc = 0.f;
#pragma unroll
    for (int i = 0; i < 8; i++) acc += dot4(r[i], qs[lane + 32 * i]);
    acc = warpSum(acc);
    if (lane == 0) g_energies[row] = acc;
}

// ---- 4. softmax over 2048 energies (single block, 1024 threads) ----
__global__ void k_softmax(float* __restrict__ dout_attn) {
    int tid = threadIdx.x;
    int lane = tid & 31, w = tid >> 5;
    float a = g_energies[tid], b = g_energies[tid + 1024];
    __shared__ float sh[32];

    float m = fmaxf(a, b);
    m = warpMax(m);
    if (lane == 0) sh[w] = m;
    __syncthreads();
    if (w == 0) {
        float v2 = sh[lane];
        v2 = warpMax(v2);
        if (lane == 0) sh[0] = v2;
    }
    __syncthreads();
    float M = sh[0];
    __syncthreads();

    float e0 = expf(a - M), e1 = expf(b - M);
    float ssum = e0 + e1;
    ssum = warpSum(ssum);
    if (lane == 0) sh[w] = ssum;
    __syncthreads();
    if (w == 0) {
        float v2 = sh[lane];
        v2 = warpSum(v2);
        if (lane == 0) sh[0] = v2;
    }
    __syncthreads();
    float inv = 1.f / sh[0];
    float w0 = e0 * inv, w1 = e1 * inv;
    g_attn[tid] = w0;        g_attn[tid + 1024] = w1;
    dout_attn[tid] = w0;     dout_attn[tid + 1024] = w1;
}

// ---- 5a. context partials: grid (4 h-chunks, SCH s-chunks) ----
__global__ void k_context_part(const float* __restrict__ enc) {
    __shared__ float sa[SDIM / SCH];          // 32 attn weights
    const int tid = threadIdx.x;              // 256
    const int s0 = blockIdx.y * (SDIM / SCH);
    if (tid < SDIM / SCH) sa[tid] = g_attn[s0 + tid];
    __syncthreads();
    const int h = blockIdx.x * 256 + tid;
    const float* e = enc + (size_t)s0 * HDIM + h;
    float acc = 0.f;
#pragma unroll 8
    for (int s = 0; s < SDIM / SCH; s++) acc += sa[s] * __ldcs(e + (size_t)s * HDIM);
    g_ctx_part[blockIdx.y * HDIM + h] = acc;
}

// ---- 5b. context reduce over SCH partials ----
__global__ void k_context_red(float* __restrict__ dout_ctx) {
    int h = blockIdx.x * 256 + threadIdx.x;
    float acc = 0.f;
#pragma unroll
    for (int c = 0; c < SCH; c++) acc += g_ctx_part[c * HDIM + h];
    g_cat[HDIM + h] = acc;
    dout_ctx[h] = acc;
}

// ---- 6. logits = W_out @ cat + b_out (warp/row; explicit 8-deep batches) ----
__global__ void __launch_bounds__(256) k_logits(const float* __restrict__ Wout,
                                                const float* __restrict__ bout) {
    __shared__ float4 cs[512];                // 8KB: full [h1, context]
    const int tid = threadIdx.x;              // 256
    cs[tid] = ((const float4*)g_cat)[tid];
    cs[tid + 256] = ((const float4*)g_cat)[tid + 256];
    __syncthreads();
    const int warp = tid >> 5, lane = tid & 31;
    const int row = blockIdx.x * 8 + warp;
    if (row >= VDIM) return;
    const float4* w4 = (const float4*)(Wout + (size_t)row * (2 * HDIM));
    float acc = 0.f;
#pragma unroll
    for (int b = 0; b < 2; b++) {
        float4 r[8];
#pragma unroll
        for (int i = 0; i < 8; i++) r[i] = __ldcs(w4 + b * 256 + lane + 32 * i);
#pragma unroll
        for (int i = 0; i < 8; i++) acc += dot4(r[i], cs[b * 256 + lane + 32 * i]);
    }
    acc = warpSum(acc);
    if (lane == 0) g_logits[row] = acc + bout[row];
}

// ---- 7. partial online (max, sumexp) over logits ----
__global__ void k_red() {
    int tid = blockIdx.x * blockDim.x + threadIdx.x;
    int lane = threadIdx.x & 31, w = threadIdx.x >> 5;
    float m = -INFINITY, ssum = 0.f;
    for (int v = tid; v < VDIM; v += NRED * 256) {
        float x = g_logits[v];
        if (x > m) { ssum = ssum * expf(m - x) + 1.f; m = x; }
        else       { ssum += expf(x - m); }
    }
#pragma unroll
    for (int o = 16; o > 0; o >>= 1) {
        float m2 = __shfl_down_sync(0xffffffffu, m, o);
        float s2 = __shfl_down_sync(0xffffffffu, ssum, o);
        float M = fmaxf(m, m2);
        ssum = ssum * expf(m - M) + s2 * expf(m2 - M);
        m = M;
    }
    __shared__ float shm[8], shs[8];
    if (lane == 0) { shm[w] = m; shs[w] = ssum; }
    __syncthreads();
    if (threadIdx.x == 0) {
        float M = shm[0], S = shs[0];
#pragma unroll
        for (int q = 1; q < 8; q++) {
            float M2 = fmaxf(M, shm[q]);
            S = S * expf(M - M2) + shs[q] * expf(shm[q] - M2);
            M = M2;
        }
        g_red_m[blockIdx.x] = M;
        g_red_s[blockIdx.x] = S;
    }
}

// ---- 8. final lse (warp 0 in-block) + write log-softmax ----
__global__ void k_out(float* __restrict__ dout) {
    __shared__ float sh_lse;
    int tid = threadIdx.x;
    if (tid < 32) {
        float m1 = g_red_m[tid],      s1 = g_red_s[tid];
        float m2 = g_red_m[tid + 32], s2 = g_red_s[tid + 32];
        float M = fmaxf(m1, m2);
        float S = s1 * expf(m1 - M) + s2 * expf(m2 - M);
#pragma unroll
        for (int o = 16; o > 0; o >>= 1) {
            float M2 = __shfl_down_sync(0xffffffffu, M, o);
            float S2 = __shfl_down_sync(0xffffffffu, S, o);
            float Mc = fmaxf(M, M2);
            S = S * expf(M - Mc) + S2 * expf(M2 - Mc);
            M = Mc;
        }
        if (tid == 0) sh_lse = M + logf(S);
    }
    __syncthreads();
    float lse = sh_lse;
    int v = blockIdx.x * blockDim.x + tid;
    if (v < VDIM) dout[v] = g_logits[v] - lse;
}

extern "C" void kernel_launch(void* const* d_in, const int* in_sizes, int n_in,
                              void* d_out, int out_size) {
    const int*   word         = (const int*)d_in[0];
    const float* last_context = (const float*)d_in[1];
    const float* last_hidden  = (const float*)d_in[2];   // (2,1,H)
    const float* enc          = (const float*)d_in[3];   // (S,1,H)
    const float* emb  = (const float*)d_in[4];
    const float* Wih0 = (const float*)d_in[5];
    const float* Whh0 = (const float*)d_in[6];
    const float* bih0 = (const float*)d_in[7];
    const float* bhh0 = (const float*)d_in[8];
    const float* Wih1 = (const float*)d_in[9];
    const float* Whh1 = (const float*)d_in[10];
    const float* bih1 = (const float*)d_in[11];
    const float* bhh1 = (const float*)d_in[12];
    const float* Wout = (const float*)d_in[13];
    const float* bout = (const float*)d_in[14];

    float* out       = (float*)d_out;
    float* out_ctx   = out + VDIM;                 // context (H)
    float* out_h0    = out + VDIM + HDIM;          // hidden[0] (H)
    float* out_h1    = out + VDIM + 2 * HDIM;      // hidden[1] (H)
    float* out_attn  = out + VDIM + 3 * HDIM;      // attn (S)

    k_gru<IN0, 0><<<HDIM, 256>>>(Wih0, Whh0, bih0, bhh0, last_hidden,         out_h0,
                                 word, emb, last_context);
    k_gru<HDIM, 1><<<HDIM, 256>>>(Wih1, Whh1, bih1, bhh1, last_hidden + HDIM, out_h1,
                                 word, emb, last_context);
    k_energy<<<SDIM / 8, 256>>>(enc);
    k_softmax<<<1, 1024>>>(out_attn);
    k_context_part<<<dim3(HDIM / 256, SCH), 256>>>(enc);
    k_context_red<<<HDIM / 256, 256>>>(out_ctx);
    k_logits<<<(VDIM + 7) / 8, 256>>>(Wout, bout);
    k_red<<<NRED, 256>>>();
    k_out<<<(VDIM + 255) / 256, 256>>>(out);
}